// round 12
// baseline (speedup 1.0000x reference)
#include <cuda_runtime.h>
#include <cuda_fp16.h>

// Problem shapes (fixed by setup_inputs): N=50000, E=1600000, F_in=128, H=4, C=32
#define MAXN 50000
#define MAXE 1600000
#define MAXET (MAXE + MAXN)
#define NBLK ((MAXN + 255) / 256)   // 196 scan blocks

// ---- static device scratch (no allocations allowed) ----
__device__ __half g_xp1h[MAXN * 128];  // layer1 projection fp16 (gather payload)
__device__ __half g_xp2h[MAXN * 32];   // layer2 projection fp16 (gather payload)
__device__ float g_als1[MAXN * 4];
__device__ float g_ald1[MAXN * 4];
__device__ float g_als2[MAXN];
__device__ float g_ald2[MAXN];
__device__ int   g_srcs[MAXET];        // CSR: src sorted by dst
__device__ int   g_deg [MAXN];
__device__ int   g_off [MAXN + 1];
__device__ int   g_cur [MAXN];
__device__ int   g_bsum[NBLK];
__device__ int   g_bpre[NBLK];
__device__ int   g_is64;

// ---------------- init: zero degrees + edge dtype detection ----------------
// int64 values < 2^31 interpreted as int32 pairs -> odd positions all zero.
__global__ void k_init(const int* __restrict__ ei32, int N) {
    int i = blockIdx.x * 256 + threadIdx.x;
    if (i < N) g_deg[i] = 0;
    if (blockIdx.x == 0) {
        __shared__ int nz;
        if (threadIdx.x == 0) nz = 0;
        __syncthreads();
        int acc = 0;
        for (int k = threadIdx.x; k < 2048; k += 256)
            acc |= ei32[2 * k + 1];
        if (acc) atomicOr(&nz, 1);
        __syncthreads();
        if (threadIdx.x == 0) g_is64 = (nz == 0) ? 1 : 0;
    }
}

__device__ __forceinline__ int load_edge(const void* ei, int is64, size_t idx) {
    if (is64) return (int)((const long long*)ei)[idx];
    return ((const int*)ei)[idx];
}

// ---------------- CSR construction ----------------

__global__ void k_count(const void* __restrict__ ei, int N, int E) {
    int is64 = g_is64;
    int total = E + N;
    for (int i = blockIdx.x * blockDim.x + threadIdx.x; i < total;
         i += gridDim.x * blockDim.x) {
        int d = (i < E) ? load_edge(ei, is64, (size_t)E + i) : (i - E);
        if ((unsigned)d >= (unsigned)N) d = 0;
        atomicAdd(&g_deg[d], 1);
    }
}

__global__ void k_scan1(int N) {
    int i = blockIdx.x * 256 + threadIdx.x;
    int lane = threadIdx.x & 31, wid = threadIdx.x >> 5;
    int v = (i < N) ? g_deg[i] : 0;
    int x = v;
    #pragma unroll
    for (int o = 1; o < 32; o <<= 1) {
        int y = __shfl_up_sync(0xffffffffu, x, o);
        if (lane >= o) x += y;
    }
    __shared__ int ws[8];
    if (lane == 31) ws[wid] = x;
    __syncthreads();
    if (wid == 0) {
        int s = (lane < 8) ? ws[lane] : 0;
        #pragma unroll
        for (int o = 1; o < 8; o <<= 1) {
            int y = __shfl_up_sync(0xffffffffu, s, o);
            if (lane >= o) s += y;
        }
        if (lane < 8) ws[lane] = s;
    }
    __syncthreads();
    int warpoff = wid ? ws[wid - 1] : 0;
    if (i < N) g_off[i] = warpoff + x - v;
    if (threadIdx.x == 255) g_bsum[blockIdx.x] = ws[7];
}

__global__ void k_scan2(int NB, int N) {
    __shared__ int sh[256];
    int t = threadIdx.x;
    int v = (t < NB) ? g_bsum[t] : 0;
    sh[t] = v;
    __syncthreads();
    for (int o = 1; o < 256; o <<= 1) {
        int y = (t >= o) ? sh[t - o] : 0;
        __syncthreads();
        sh[t] += y;
        __syncthreads();
    }
    if (t < NB) g_bpre[t] = sh[t] - v;
    if (t == 255) g_off[N] = sh[255];
}

__global__ void k_scan3(int N) {
    int i = blockIdx.x * 256 + threadIdx.x;
    if (i < N) {
        int o = g_off[i] + g_bpre[blockIdx.x];
        g_off[i] = o;
        g_cur[i] = o;
    }
}

__global__ void k_scatter(const void* __restrict__ ei, int N, int E) {
    int is64 = g_is64;
    int total = E + N;
    for (int i = blockIdx.x * blockDim.x + threadIdx.x; i < total;
         i += gridDim.x * blockDim.x) {
        int s, d;
        if (i < E) {
            s = load_edge(ei, is64, (size_t)i);
            d = load_edge(ei, is64, (size_t)E + i);
        } else {
            s = d = i - E;
        }
        if ((unsigned)s >= (unsigned)N) s = 0;
        if ((unsigned)d >= (unsigned)N) d = 0;
        int p = atomicAdd(&g_cur[d], 1);
        g_srcs[p] = s;
    }
}

// ---------------- layer 1: GEMM xp1 = x @ W1, fused attention logits ----------------
// 256 threads, 32 rows x 128 cols per block; epilogue computes als1/ald1 via
// warp reductions over the register accumulators (lane tx = channel, j = head).
__global__ void k_gemm1(const float* __restrict__ x, const float* __restrict__ W,
                        const float* __restrict__ a_src, const float* __restrict__ a_dst,
                        int N) {
    __shared__ float xs[32][33];
    __shared__ float ws[32][128];
    int tid = threadIdx.x;
    int tx = tid & 31, ty = tid >> 5;
    int row0 = blockIdx.x * 32;
    float acc[4][4] = {};
    for (int k0 = 0; k0 < 128; k0 += 32) {
        #pragma unroll
        for (int i = 0; i < 16; ++i) {
            int idx = tid + i * 256;
            int kk = idx >> 7, cc = idx & 127;
            ws[kk][cc] = W[(size_t)(k0 + kk) * 128 + cc];
        }
        #pragma unroll
        for (int i = 0; i < 4; ++i) {
            int idx = tid + i * 256;
            int rr = idx >> 5, kk = idx & 31;
            int r = row0 + rr;
            xs[rr][kk] = (r < N) ? x[(size_t)r * 128 + k0 + kk] : 0.f;
        }
        __syncthreads();
        #pragma unroll
        for (int kk = 0; kk < 32; ++kk) {
            float a[4], b[4];
            #pragma unroll
            for (int i = 0; i < 4; ++i) a[i] = xs[ty * 4 + i][kk];
            #pragma unroll
            for (int j = 0; j < 4; ++j) b[j] = ws[kk][tx + j * 32];
            #pragma unroll
            for (int i = 0; i < 4; ++i)
                #pragma unroll
                for (int j = 0; j < 4; ++j) acc[i][j] += a[i] * b[j];
        }
        __syncthreads();
    }
    // store fp16 payload + fused logits
    #pragma unroll
    for (int i = 0; i < 4; ++i) {
        int r = row0 + ty * 4 + i;
        if (r >= N) continue;
        #pragma unroll
        for (int j = 0; j < 4; ++j)
            g_xp1h[(size_t)r * 128 + tx + j * 32] = __float2half(acc[i][j]);
        #pragma unroll
        for (int j = 0; j < 4; ++j) {
            float s = acc[i][j] * a_src[j * 32 + tx];
            float d = acc[i][j] * a_dst[j * 32 + tx];
            #pragma unroll
            for (int o = 16; o; o >>= 1) {
                s += __shfl_xor_sync(0xffffffffu, s, o);
                d += __shfl_xor_sync(0xffffffffu, d, o);
            }
            if (tx == 0) { g_als1[r * 4 + j] = s; g_ald1[r * 4 + j] = d; }
        }
    }
}

// layer-1 softmax + aggregation (one pass, smem ex staging) + ELU
// + fused layer-2 projection & logits. One warp per destination node.
__global__ void k_agg1(const float* __restrict__ b1, const float* __restrict__ W2,
                       const float* __restrict__ a_src2, const float* __restrict__ a_dst2,
                       int N) {
    __shared__ float  ws[4096];       // W2 [128][32]
    __shared__ float  hs[8][128];     // per-warp h row
    __shared__ float4 exs[8][32];     // per-warp per-chunk exp numerators
    int tid = threadIdx.x;
    for (int i = tid; i < 4096; i += 256) ws[i] = W2[i];
    __syncthreads();

    int w = (blockIdx.x * 256 + tid) >> 5;
    int lane = tid & 31, wid = tid >> 5;
    if (w >= N) return;
    int beg = g_off[w], end = g_off[w + 1];
    float ald0 = g_ald1[w * 4 + 0], ald1v = g_ald1[w * 4 + 1];
    float ald2 = g_ald1[w * 4 + 2], ald3 = g_ald1[w * 4 + 3];
    float den0 = 0.f, den1 = 0.f, den2 = 0.f, den3 = 0.f;
    bool lo16 = (lane < 16);
    float accA0 = 0.f, accA1 = 0.f, accB0 = 0.f, accB1 = 0.f;

    for (int base = beg; base < end; base += 32) {
        int cnt = end - base; if (cnt > 32) cnt = 32;
        int sv = 0;
        // phase A: lane-parallel exp numerators into smem + den accumulation
        if (lane < cnt) {
            sv = g_srcs[base + lane];
            float4 al = *(const float4*)(g_als1 + (size_t)sv * 4);
            float t0 = al.x + ald0;  t0 = t0 > 0.f ? t0 : 0.2f * t0;
            float t1 = al.y + ald1v; t1 = t1 > 0.f ? t1 : 0.2f * t1;
            float t2 = al.z + ald2;  t2 = t2 > 0.f ? t2 : 0.2f * t2;
            float t3 = al.w + ald3;  t3 = t3 > 0.f ? t3 : 0.2f * t3;
            float4 ex;
            ex.x = __expf(t0); ex.y = __expf(t1); ex.z = __expf(t2); ex.w = __expf(t3);
            exs[wid][lane] = ex;
            den0 += ex.x; den1 += ex.y; den2 += ex.z; den3 += ex.w;
        }
        __syncwarp();
        // phase B: broadcast edges, half2 payload gathers
        for (int k = 0; k < cnt; ++k) {
            int s = __shfl_sync(0xffffffffu, sv, k);
            float4 e4 = exs[wid][k];
            const __half2* xr = (const __half2*)(g_xp1h + (size_t)s * 128);
            float2 fa = __half22float2(xr[lane]);       // channels 2l,2l+1
            float2 fb = __half22float2(xr[32 + lane]);  // channels 64+2l,64+2l+1
            float wa = lo16 ? e4.x : e4.y;
            float wb = lo16 ? e4.z : e4.w;
            accA0 += fa.x * wa; accA1 += fa.y * wa;
            accB0 += fb.x * wb; accB1 += fb.y * wb;
        }
        __syncwarp();
    }
    #pragma unroll
    for (int o = 16; o; o >>= 1) {
        den0 += __shfl_xor_sync(0xffffffffu, den0, o);
        den1 += __shfl_xor_sync(0xffffffffu, den1, o);
        den2 += __shfl_xor_sync(0xffffffffu, den2, o);
        den3 += __shfl_xor_sync(0xffffffffu, den3, o);
    }
    float invA = 1.f / ((lo16 ? den0 : den1) + 1e-16f);
    float invB = 1.f / ((lo16 ? den2 : den3) + 1e-16f);
    int cA = 2 * lane, cB = 64 + 2 * lane;
    float v, hA0, hA1, hB0, hB1;
    v = accA0 * invA + b1[cA];     hA0 = v > 0.f ? v : (__expf(v) - 1.f);
    v = accA1 * invA + b1[cA + 1]; hA1 = v > 0.f ? v : (__expf(v) - 1.f);
    v = accB0 * invB + b1[cB];     hB0 = v > 0.f ? v : (__expf(v) - 1.f);
    v = accB1 * invB + b1[cB + 1]; hB1 = v > 0.f ? v : (__expf(v) - 1.f);

    // stage h row in shared, fused layer-2 projection (fp32)
    hs[wid][cA]     = hA0;
    hs[wid][cA + 1] = hA1;
    hs[wid][cB]     = hB0;
    hs[wid][cB + 1] = hB1;
    __syncwarp();
    float acc2 = 0.f;
    #pragma unroll
    for (int k4 = 0; k4 < 32; ++k4) {
        float4 h4 = *(const float4*)&hs[wid][k4 * 4];
        acc2 += h4.x * ws[(k4 * 4 + 0) * 32 + lane];
        acc2 += h4.y * ws[(k4 * 4 + 1) * 32 + lane];
        acc2 += h4.z * ws[(k4 * 4 + 2) * 32 + lane];
        acc2 += h4.w * ws[(k4 * 4 + 3) * 32 + lane];
    }
    g_xp2h[(size_t)w * 32 + lane] = __float2half(acc2);
    float s2 = acc2 * a_src2[lane];
    float d2 = acc2 * a_dst2[lane];
    #pragma unroll
    for (int o = 16; o; o >>= 1) {
        s2 += __shfl_xor_sync(0xffffffffu, s2, o);
        d2 += __shfl_xor_sync(0xffffffffu, d2, o);
    }
    if (lane == 0) { g_als2[w] = s2; g_ald2[w] = d2; }
}

// layer-2 aggregation (one pass, smem ex staging), warp per node.
__global__ void k_agg2(const float* __restrict__ b2, float* __restrict__ out, int N) {
    __shared__ float exs[8][32];
    int tid = threadIdx.x;
    int w = (blockIdx.x * 256 + tid) >> 5;
    int lane = tid & 31, wid = tid >> 5;
    if (w >= N) return;
    int beg = g_off[w], end = g_off[w + 1];
    float ald = g_ald2[w];
    float den = 0.f, acc = 0.f;
    for (int base = beg; base < end; base += 32) {
        int cnt = end - base; if (cnt > 32) cnt = 32;
        int sv = 0;
        if (lane < cnt) {
            sv = g_srcs[base + lane];
            float t = g_als2[sv] + ald;
            t = t > 0.f ? t : 0.2f * t;
            float ex = __expf(t);
            exs[wid][lane] = ex;
            den += ex;
        }
        __syncwarp();
        for (int k = 0; k < cnt; ++k) {
            int s = __shfl_sync(0xffffffffu, sv, k);
            float e = exs[wid][k];
            acc += __half2float(g_xp2h[(size_t)s * 32 + lane]) * e;
        }
        __syncwarp();
    }
    #pragma unroll
    for (int o = 16; o; o >>= 1) den += __shfl_xor_sync(0xffffffffu, den, o);
    float inv = 1.f / (den + 1e-16f);
    out[(size_t)w * 32 + lane] = acc * inv + b2[lane];
}

extern "C" void kernel_launch(void* const* d_in, const int* in_sizes, int n_in,
                              void* d_out, int out_size) {
    const float* x      = (const float*)d_in[0];
    const void*  ei     = d_in[1];
    const float* W1     = (const float*)d_in[2];
    const float* a_src1 = (const float*)d_in[3];
    const float* a_dst1 = (const float*)d_in[4];
    const float* b1     = (const float*)d_in[5];
    const float* W2     = (const float*)d_in[6];
    const float* a_src2 = (const float*)d_in[7];
    const float* a_dst2 = (const float*)d_in[8];
    const float* b2     = (const float*)d_in[9];
    float* out = (float*)d_out;

    int N = in_sizes[0] / 128;  // 50000
    int E = in_sizes[1] / 2;    // 1600000
    int NB = (N + 255) / 256;   // 196

    static cudaStream_t s2 = nullptr;
    static cudaEvent_t ev_fork = nullptr, ev_join = nullptr;
    if (!s2) {
        cudaStreamCreateWithFlags(&s2, cudaStreamNonBlocking);
        cudaEventCreateWithFlags(&ev_fork, cudaEventDisableTiming);
        cudaEventCreateWithFlags(&ev_join, cudaEventDisableTiming);
    }

    // ---- fork: GEMM1(+logits) on side stream, CSR build on main stream ----
    cudaEventRecord(ev_fork, 0);
    cudaStreamWaitEvent(s2, ev_fork, 0);

    k_gemm1<<<(N + 31) / 32, 256, 0, s2>>>(x, W1, a_src1, a_dst1, N);
    cudaEventRecord(ev_join, s2);

    // CSR build
    k_init   <<<NB, 256>>>((const int*)ei, N);
    k_count  <<<2048, 256>>>(ei, N, E);
    k_scan1  <<<NB, 256>>>(N);
    k_scan2  <<<1, 256>>>(NB, N);
    k_scan3  <<<NB, 256>>>(N);
    k_scatter<<<2048, 256>>>(ei, N, E);

    // ---- join: agg1 needs both CSR and xp1/logits ----
    cudaStreamWaitEvent(0, ev_join, 0);

    // layer 1 aggregation + fused layer-2 projection/logits
    k_agg1<<<(N + 7) / 8, 256>>>(b1, W2, a_src2, a_dst2, N);

    // layer 2 aggregation
    k_agg2<<<(N + 7) / 8, 256>>>(b2, out, N);
}

// round 13
// speedup vs baseline: 1.5162x; 1.5162x over previous
#include <cuda_runtime.h>
#include <cuda_fp16.h>

// Problem shapes (fixed by setup_inputs): N=50000, E=1600000, F_in=128, H=4, C=32
#define MAXN 50000
#define MAXE 1600000
#define MAXET (MAXE + MAXN)
#define NBLK ((MAXN + 255) / 256)   // 196 scan blocks

// ---- static device scratch (no allocations allowed) ----
__device__ __half g_xp1h[MAXN * 128];  // layer1 projection fp16 (gather payload)
__device__ __half g_xp2h[MAXN * 32];   // layer2 projection fp16 (gather payload)
__device__ float  g_als1[MAXN * 4];
__device__ float  g_ald1[MAXN * 4];
__device__ float  g_als2[MAXN];
__device__ float  g_ald2[MAXN];
__device__ uint2  g_ex4h[MAXET];       // per-edge exp numerators, 4 x half (agg1)
__device__ __half g_exh [MAXET];       // per-edge exp numerators (agg2)
__device__ int    g_srcs[MAXET];       // CSR: src sorted by dst
__device__ int    g_deg [MAXN];
__device__ int    g_off [MAXN + 1];
__device__ int    g_cur [MAXN];
__device__ int    g_bsum[NBLK];
__device__ int    g_bpre[NBLK];
__device__ int    g_is64;

// ---------------- init: zero degrees + edge dtype detection ----------------
// int64 values < 2^31 interpreted as int32 pairs -> odd positions all zero.
__global__ void k_init(const int* __restrict__ ei32, int N) {
    int i = blockIdx.x * 256 + threadIdx.x;
    if (i < N) g_deg[i] = 0;
    if (blockIdx.x == 0) {
        __shared__ int nz;
        if (threadIdx.x == 0) nz = 0;
        __syncthreads();
        int acc = 0;
        for (int k = threadIdx.x; k < 2048; k += 256)
            acc |= ei32[2 * k + 1];
        if (acc) atomicOr(&nz, 1);
        __syncthreads();
        if (threadIdx.x == 0) g_is64 = (nz == 0) ? 1 : 0;
    }
}

__device__ __forceinline__ int load_edge(const void* ei, int is64, size_t idx) {
    if (is64) return (int)((const long long*)ei)[idx];
    return ((const int*)ei)[idx];
}

// ---------------- CSR construction ----------------

__global__ void k_count(const void* __restrict__ ei, int N, int E) {
    int is64 = g_is64;
    int total = E + N;
    for (int i = blockIdx.x * blockDim.x + threadIdx.x; i < total;
         i += gridDim.x * blockDim.x) {
        int d = (i < E) ? load_edge(ei, is64, (size_t)E + i) : (i - E);
        if ((unsigned)d >= (unsigned)N) d = 0;
        atomicAdd(&g_deg[d], 1);
    }
}

__global__ void k_scan1(int N) {
    int i = blockIdx.x * 256 + threadIdx.x;
    int lane = threadIdx.x & 31, wid = threadIdx.x >> 5;
    int v = (i < N) ? g_deg[i] : 0;
    int x = v;
    #pragma unroll
    for (int o = 1; o < 32; o <<= 1) {
        int y = __shfl_up_sync(0xffffffffu, x, o);
        if (lane >= o) x += y;
    }
    __shared__ int ws[8];
    if (lane == 31) ws[wid] = x;
    __syncthreads();
    if (wid == 0) {
        int s = (lane < 8) ? ws[lane] : 0;
        #pragma unroll
        for (int o = 1; o < 8; o <<= 1) {
            int y = __shfl_up_sync(0xffffffffu, s, o);
            if (lane >= o) s += y;
        }
        if (lane < 8) ws[lane] = s;
    }
    __syncthreads();
    int warpoff = wid ? ws[wid - 1] : 0;
    if (i < N) g_off[i] = warpoff + x - v;
    if (threadIdx.x == 255) g_bsum[blockIdx.x] = ws[7];
}

__global__ void k_scan2(int NB, int N) {
    __shared__ int sh[256];
    int t = threadIdx.x;
    int v = (t < NB) ? g_bsum[t] : 0;
    sh[t] = v;
    __syncthreads();
    for (int o = 1; o < 256; o <<= 1) {
        int y = (t >= o) ? sh[t - o] : 0;
        __syncthreads();
        sh[t] += y;
        __syncthreads();
    }
    if (t < NB) g_bpre[t] = sh[t] - v;
    if (t == 255) g_off[N] = sh[255];
}

__global__ void k_scan3(int N) {
    int i = blockIdx.x * 256 + threadIdx.x;
    if (i < N) {
        int o = g_off[i] + g_bpre[blockIdx.x];
        g_off[i] = o;
        g_cur[i] = o;
    }
}

__global__ void k_scatter(const void* __restrict__ ei, int N, int E) {
    int is64 = g_is64;
    int total = E + N;
    for (int i = blockIdx.x * blockDim.x + threadIdx.x; i < total;
         i += gridDim.x * blockDim.x) {
        int s, d;
        if (i < E) {
            s = load_edge(ei, is64, (size_t)i);
            d = load_edge(ei, is64, (size_t)E + i);
        } else {
            s = d = i - E;
        }
        if ((unsigned)s >= (unsigned)N) s = 0;
        if ((unsigned)d >= (unsigned)N) d = 0;
        int p = atomicAdd(&g_cur[d], 1);
        g_srcs[p] = s;
    }
}

// ---------------- layer 1: GEMM xp1 = x @ W1, fused attention logits ----------------
__global__ void k_gemm1(const float* __restrict__ x, const float* __restrict__ W,
                        const float* __restrict__ a_src, const float* __restrict__ a_dst,
                        int N) {
    __shared__ float xs[32][33];
    __shared__ float ws[32][128];
    int tid = threadIdx.x;
    int tx = tid & 31, ty = tid >> 5;
    int row0 = blockIdx.x * 32;
    float acc[4][4] = {};
    for (int k0 = 0; k0 < 128; k0 += 32) {
        #pragma unroll
        for (int i = 0; i < 16; ++i) {
            int idx = tid + i * 256;
            int kk = idx >> 7, cc = idx & 127;
            ws[kk][cc] = W[(size_t)(k0 + kk) * 128 + cc];
        }
        #pragma unroll
        for (int i = 0; i < 4; ++i) {
            int idx = tid + i * 256;
            int rr = idx >> 5, kk = idx & 31;
            int r = row0 + rr;
            xs[rr][kk] = (r < N) ? x[(size_t)r * 128 + k0 + kk] : 0.f;
        }
        __syncthreads();
        #pragma unroll
        for (int kk = 0; kk < 32; ++kk) {
            float a[4], b[4];
            #pragma unroll
            for (int i = 0; i < 4; ++i) a[i] = xs[ty * 4 + i][kk];
            #pragma unroll
            for (int j = 0; j < 4; ++j) b[j] = ws[kk][tx + j * 32];
            #pragma unroll
            for (int i = 0; i < 4; ++i)
                #pragma unroll
                for (int j = 0; j < 4; ++j) acc[i][j] += a[i] * b[j];
        }
        __syncthreads();
    }
    // store fp16 payload + fused logits (lane tx = channel, j = head)
    #pragma unroll
    for (int i = 0; i < 4; ++i) {
        int r = row0 + ty * 4 + i;
        if (r >= N) continue;
        #pragma unroll
        for (int j = 0; j < 4; ++j)
            g_xp1h[(size_t)r * 128 + tx + j * 32] = __float2half(acc[i][j]);
        #pragma unroll
        for (int j = 0; j < 4; ++j) {
            float s = acc[i][j] * a_src[j * 32 + tx];
            float d = acc[i][j] * a_dst[j * 32 + tx];
            #pragma unroll
            for (int o = 16; o; o >>= 1) {
                s += __shfl_xor_sync(0xffffffffu, s, o);
                d += __shfl_xor_sync(0xffffffffu, d, o);
            }
            if (tx == 0) { g_als1[r * 4 + j] = s; g_ald1[r * 4 + j] = d; }
        }
    }
}

// layer-1 softmax + aggregation (two-pass, half2 gathers) + ELU
// + fused layer-2 projection & logits. One warp per destination node.
__global__ void k_agg1(const float* __restrict__ b1, const float* __restrict__ W2,
                       const float* __restrict__ a_src2, const float* __restrict__ a_dst2,
                       int N) {
    __shared__ float ws[4096];      // W2 [128][32]
    __shared__ float hs[8][128];    // per-warp h row
    int tid = threadIdx.x;
    for (int i = tid; i < 4096; i += 256) ws[i] = W2[i];
    __syncthreads();

    int w = (blockIdx.x * 256 + tid) >> 5;
    int lane = tid & 31, wid = tid >> 5;
    if (w >= N) return;
    int beg = g_off[w], end = g_off[w + 1];
    float ald0 = g_ald1[w * 4 + 0], ald1v = g_ald1[w * 4 + 1];
    float ald2 = g_ald1[w * 4 + 2], ald3 = g_ald1[w * 4 + 3];
    float den0 = 0.f, den1 = 0.f, den2 = 0.f, den3 = 0.f;
    // pass 1: lane-parallel exp numerators (stored as packed half4) + denominators
    for (int e = beg + lane; e < end; e += 32) {
        int s = g_srcs[e];
        float4 al = *(const float4*)(g_als1 + (size_t)s * 4);
        float t0 = al.x + ald0;  t0 = t0 > 0.f ? t0 : 0.2f * t0;
        float t1 = al.y + ald1v; t1 = t1 > 0.f ? t1 : 0.2f * t1;
        float t2 = al.z + ald2;  t2 = t2 > 0.f ? t2 : 0.2f * t2;
        float t3 = al.w + ald3;  t3 = t3 > 0.f ? t3 : 0.2f * t3;
        __half2 p01 = __floats2half2_rn(__expf(t0), __expf(t1));
        __half2 p23 = __floats2half2_rn(__expf(t2), __expf(t3));
        uint2 u;
        u.x = *(const unsigned*)&p01;
        u.y = *(const unsigned*)&p23;
        g_ex4h[e] = u;
        // accumulate den from the ROUNDED values so num/den quantization cancels
        float2 f01 = __half22float2(p01);
        float2 f23 = __half22float2(p23);
        den0 += f01.x; den1 += f01.y; den2 += f23.x; den3 += f23.y;
    }
    __syncwarp();
    #pragma unroll
    for (int o = 16; o; o >>= 1) {
        den0 += __shfl_xor_sync(0xffffffffu, den0, o);
        den1 += __shfl_xor_sync(0xffffffffu, den1, o);
        den2 += __shfl_xor_sync(0xffffffffu, den2, o);
        den3 += __shfl_xor_sync(0xffffffffu, den3, o);
    }
    bool lo16 = (lane < 16);
    float invA = 1.f / ((lo16 ? den0 : den1) + 1e-16f);
    float invB = 1.f / ((lo16 ? den2 : den3) + 1e-16f);
    // pass 2: streaming half2 payload gathers; lane l owns channels
    // {2l, 2l+1} (heads 0/1) and {64+2l, 64+2l+1} (heads 2/3).
    float accA0 = 0.f, accA1 = 0.f, accB0 = 0.f, accB1 = 0.f;
    for (int e = beg; e < end; ++e) {
        int s = g_srcs[e];                   // broadcast
        uint2 u = g_ex4h[e];                 // broadcast
        __half2 p01 = *(const __half2*)&u.x;
        __half2 p23 = *(const __half2*)&u.y;
        float2 e01 = __half22float2(p01);
        float2 e23 = __half22float2(p23);
        const __half2* xr = (const __half2*)(g_xp1h + (size_t)s * 128);
        float2 fa = __half22float2(xr[lane]);       // channels 2l,2l+1
        float2 fb = __half22float2(xr[32 + lane]);  // channels 64+2l,64+2l+1
        float wa = lo16 ? e01.x : e01.y;
        float wb = lo16 ? e23.x : e23.y;
        accA0 += fa.x * wa; accA1 += fa.y * wa;
        accB0 += fb.x * wb; accB1 += fb.y * wb;
    }
    int cA = 2 * lane, cB = 64 + 2 * lane;
    float v, hA0, hA1, hB0, hB1;
    v = accA0 * invA + b1[cA];     hA0 = v > 0.f ? v : (__expf(v) - 1.f);
    v = accA1 * invA + b1[cA + 1]; hA1 = v > 0.f ? v : (__expf(v) - 1.f);
    v = accB0 * invB + b1[cB];     hB0 = v > 0.f ? v : (__expf(v) - 1.f);
    v = accB1 * invB + b1[cB + 1]; hB1 = v > 0.f ? v : (__expf(v) - 1.f);

    // stage h row in shared, fused layer-2 projection (fp32)
    hs[wid][cA]     = hA0;
    hs[wid][cA + 1] = hA1;
    hs[wid][cB]     = hB0;
    hs[wid][cB + 1] = hB1;
    __syncwarp();
    float acc2 = 0.f;
    #pragma unroll
    for (int k4 = 0; k4 < 32; ++k4) {
        float4 h4 = *(const float4*)&hs[wid][k4 * 4];
        acc2 += h4.x * ws[(k4 * 4 + 0) * 32 + lane];
        acc2 += h4.y * ws[(k4 * 4 + 1) * 32 + lane];
        acc2 += h4.z * ws[(k4 * 4 + 2) * 32 + lane];
        acc2 += h4.w * ws[(k4 * 4 + 3) * 32 + lane];
    }
    g_xp2h[(size_t)w * 32 + lane] = __float2half(acc2);
    float s2 = acc2 * a_src2[lane];
    float d2 = acc2 * a_dst2[lane];
    #pragma unroll
    for (int o = 16; o; o >>= 1) {
        s2 += __shfl_xor_sync(0xffffffffu, s2, o);
        d2 += __shfl_xor_sync(0xffffffffu, d2, o);
    }
    if (lane == 0) { g_als2[w] = s2; g_ald2[w] = d2; }
}

// layer-2 aggregation (two-pass), warp per node, fp16 gathers, fp32 math.
__global__ void k_agg2(const float* __restrict__ b2, float* __restrict__ out, int N) {
    int w = (blockIdx.x * blockDim.x + threadIdx.x) >> 5;
    int lane = threadIdx.x & 31;
    if (w >= N) return;
    int beg = g_off[w], end = g_off[w + 1];
    float ald = g_ald2[w];
    float den = 0.f;
    for (int e = beg + lane; e < end; e += 32) {
        int s = g_srcs[e];
        float t = g_als2[s] + ald;
        t = t > 0.f ? t : 0.2f * t;
        __half h = __float2half_rn(__expf(t));
        g_exh[e] = h;
        den += __half2float(h);   // rounded, so num/den quantization cancels
    }
    __syncwarp();
    #pragma unroll
    for (int o = 16; o; o >>= 1) den += __shfl_xor_sync(0xffffffffu, den, o);
    float inv = 1.f / (den + 1e-16f);
    float acc = 0.f;
    for (int e = beg; e < end; ++e) {
        int s = g_srcs[e];
        acc += __half2float(g_xp2h[(size_t)s * 32 + lane]) * __half2float(g_exh[e]);
    }
    out[(size_t)w * 32 + lane] = acc * inv + b2[lane];
}

extern "C" void kernel_launch(void* const* d_in, const int* in_sizes, int n_in,
                              void* d_out, int out_size) {
    const float* x      = (const float*)d_in[0];
    const void*  ei     = d_in[1];
    const float* W1     = (const float*)d_in[2];
    const float* a_src1 = (const float*)d_in[3];
    const float* a_dst1 = (const float*)d_in[4];
    const float* b1     = (const float*)d_in[5];
    const float* W2     = (const float*)d_in[6];
    const float* a_src2 = (const float*)d_in[7];
    const float* a_dst2 = (const float*)d_in[8];
    const float* b2     = (const float*)d_in[9];
    float* out = (float*)d_out;

    int N = in_sizes[0] / 128;  // 50000
    int E = in_sizes[1] / 2;    // 1600000
    int NB = (N + 255) / 256;   // 196

    static cudaStream_t s2 = nullptr;
    static cudaEvent_t ev_fork = nullptr, ev_join = nullptr;
    if (!s2) {
        cudaStreamCreateWithFlags(&s2, cudaStreamNonBlocking);
        cudaEventCreateWithFlags(&ev_fork, cudaEventDisableTiming);
        cudaEventCreateWithFlags(&ev_join, cudaEventDisableTiming);
    }

    // ---- fork: GEMM1(+logits) on side stream, CSR build on main stream ----
    cudaEventRecord(ev_fork, 0);
    cudaStreamWaitEvent(s2, ev_fork, 0);

    k_gemm1<<<(N + 31) / 32, 256, 0, s2>>>(x, W1, a_src1, a_dst1, N);
    cudaEventRecord(ev_join, s2);

    // CSR build
    k_init   <<<NB, 256>>>((const int*)ei, N);
    k_count  <<<2048, 256>>>(ei, N, E);
    k_scan1  <<<NB, 256>>>(N);
    k_scan2  <<<1, 256>>>(NB, N);
    k_scan3  <<<NB, 256>>>(N);
    k_scatter<<<2048, 256>>>(ei, N, E);

    // ---- join: agg1 needs both CSR and xp1/logits ----
    cudaStreamWaitEvent(0, ev_join, 0);

    // layer 1 aggregation + fused layer-2 projection/logits
    k_agg1<<<(N + 7) / 8, 256>>>(b1, W2, a_src2, a_dst2, N);

    // layer 2 aggregation
    k_agg2<<<(N + 7) / 8, 256>>>(b2, out, N);
}